// round 14
// baseline (speedup 1.0000x reference)
#include <cuda_runtime.h>
#include <cuda_bf16.h>
#include <cstdint>

#define B_ 4
#define N_ 32768
#define C_ 256
#define H_ 8
#define CH_ 64
#define M_ 64
#define INNER_ 512
#define ROWS_ (B_*N_)          // 131072
#define BH_ 32
#define PASS_SW ((size_t)BH_ * N_ * M_)

// ================= static scratch (2 passes: pass0 = x, pass1 = x_cross) =================
__device__ __nv_bfloat16 d_fx_h[(size_t)2 * ROWS_ * 512];
__device__ __nv_bfloat16 d_fx_l[(size_t)2 * ROWS_ * 512];
__device__ __nv_bfloat16 d_sw_h[(size_t)2 * BH_ * N_ * M_];
__device__ __nv_bfloat16 d_sw_l[(size_t)2 * BH_ * N_ * M_];
__device__ __nv_bfloat16 d_xs_h[(size_t)2 * ROWS_ * 256];
__device__ __nv_bfloat16 d_xs_l[(size_t)2 * ROWS_ * 256];
__device__ float d_tokx[BH_ * M_ * CH_];
__device__ float d_tokc[BH_ * M_ * CH_];
__device__ float d_csx[BH_ * M_];
__device__ float d_csc[BH_ * M_];
__device__ float d_outsc[BH_ * M_ * CH_];
__device__ float d_bls[INNER_];
__device__ __nv_bfloat16 d_wfx_h[INNER_ * C_];
__device__ __nv_bfloat16 d_wfx_l[INNER_ * C_];
__device__ __nv_bfloat16 d_wls_h[INNER_ * C_];
__device__ __nv_bfloat16 d_wls_l[INNER_ * C_];
__device__ __nv_bfloat16 d_wot_h[B_ * C_ * INNER_];
__device__ __nv_bfloat16 d_wot_l[B_ * C_ * INNER_];

// ================= helpers =================
__device__ __forceinline__ uint32_t smem_u32(const void* p) {
    uint32_t a;
    asm("{ .reg .u64 t; cvta.to.shared.u64 t, %1; cvt.u32.u64 %0, t; }" : "=r"(a) : "l"(p));
    return a;
}
__device__ __forceinline__ void ldsm4(uint32_t* r, uint32_t addr) {
    asm volatile("ldmatrix.sync.aligned.m8n8.x4.shared.b16 {%0,%1,%2,%3}, [%4];"
                 : "=r"(r[0]), "=r"(r[1]), "=r"(r[2]), "=r"(r[3]) : "r"(addr));
}
__device__ __forceinline__ void ldsm4t(uint32_t* r, uint32_t addr) {
    asm volatile("ldmatrix.sync.aligned.m8n8.x4.trans.shared.b16 {%0,%1,%2,%3}, [%4];"
                 : "=r"(r[0]), "=r"(r[1]), "=r"(r[2]), "=r"(r[3]) : "r"(addr));
}
__device__ __forceinline__ void mma16816(float* c, const uint32_t* a, const uint32_t* b) {
    asm volatile("mma.sync.aligned.m16n8k16.row.col.f32.bf16.bf16.f32 "
                 "{%0,%1,%2,%3}, {%4,%5,%6,%7}, {%8,%9}, {%0,%1,%2,%3};"
                 : "+f"(c[0]), "+f"(c[1]), "+f"(c[2]), "+f"(c[3])
                 : "r"(a[0]), "r"(a[1]), "r"(a[2]), "r"(a[3]), "r"(b[0]), "r"(b[1]));
}
__device__ __forceinline__ void split2(float x, float y, uint32_t& hi, uint32_t& lo) {
    __nv_bfloat16 hx = __float2bfloat16(x), hy = __float2bfloat16(y);
    float rx = x - __bfloat162float(hx), ry = y - __bfloat162float(hy);
    __nv_bfloat16 lx = __float2bfloat16(rx), ly = __float2bfloat16(ry);
    hi = (uint32_t)__bfloat16_as_ushort(hx) | ((uint32_t)__bfloat16_as_ushort(hy) << 16);
    lo = (uint32_t)__bfloat16_as_ushort(lx) | ((uint32_t)__bfloat16_as_ushort(ly) << 16);
}
__device__ __forceinline__ float sum2bf(uint32_t r) {
    __nv_bfloat162 v = *reinterpret_cast<__nv_bfloat162*>(&r);
    return __bfloat162float(v.x) + __bfloat162float(v.y);
}
__device__ __forceinline__ void cpa16(uint32_t dst, const void* src) {
    asm volatile("cp.async.cg.shared.global [%0], [%1], 16;" :: "r"(dst), "l"(src));
}
#define CP_COMMIT() asm volatile("cp.async.commit_group;" ::: "memory")
#define CP_WAIT1()  asm volatile("cp.async.wait_group 1;" ::: "memory")

#define STAGE_BYTES 32768
#define GEMM_SMEM   98304
#define SWX64(r, byte) ((uint32_t)((r) * 64 + ((byte) ^ ((((r) >> 1) & 3) << 4))))
#define SWX(r, byte) ((uint32_t)((r) * 128 + ((byte) ^ (((r) & 7) << 4))))

#define GEMM_PROLOG() \
    extern __shared__ char smem[]; \
    const uint32_t sb = smem_u32(smem); \
    const int t = threadIdx.x; \
    const int w = t >> 5, lane = t & 31; \
    const int wm = (w & 3) * 32, wn = (w >> 2) * 64; \
    const int g = lane >> 2, tq = lane & 3; \
    const int ar_ = lane & 15, akh_ = lane >> 4; \
    const int qd_ = lane >> 3, bl8_ = lane & 7; \
    uint32_t abase[2], axr[2], bbase[4], bxr[4]; \
    _Pragma("unroll") for (int mi = 0; mi < 2; mi++) { \
        int row = wm + mi * 16 + ar_; \
        abase[mi] = row * 64; axr[mi] = ((row >> 1) & 3) << 4; \
    } \
    _Pragma("unroll") for (int nb = 0; nb < 4; nb++) { \
        int row = wn + nb * 16 + (qd_ >> 1) * 8 + bl8_; \
        bbase[nb] = row * 64; bxr[nb] = ((row >> 1) & 3) << 4; \
    } \
    const uint32_t bk16_ = (qd_ & 1) * 16; \
    const uint32_t ak16_ = akh_ * 16; \
    float c[2][8][4]; \
    _Pragma("unroll") for (int mi = 0; mi < 2; mi++) \
    _Pragma("unroll") for (int ni = 0; ni < 8; ni++) \
    _Pragma("unroll") for (int q = 0; q < 4; q++) c[mi][ni][q] = 0.f;

#define GEMM_COMPUTE_CHUNK32(soff) \
    _Pragma("unroll") for (int ks = 0; ks < 2; ks++) { \
        uint32_t ah[2][4], al[2][4]; \
        const uint32_t ka = ks * 32 + ak16_; \
        const uint32_t kb = ks * 32 + bk16_; \
        _Pragma("unroll") for (int mi = 0; mi < 2; mi++) { \
            uint32_t off = (soff) + abase[mi] + (ka ^ axr[mi]); \
            ldsm4(ah[mi], sb + off); \
            ldsm4(al[mi], sb + 8192 + off); \
        } \
        _Pragma("unroll") for (int half = 0; half < 2; half++) { \
            uint32_t bh[4][2], bl[4][2]; \
            _Pragma("unroll") for (int nb = 0; nb < 2; nb++) { \
                uint32_t off = (soff) + bbase[half * 2 + nb] + (kb ^ bxr[half * 2 + nb]); \
                uint32_t rh[4], rl[4]; \
                ldsm4(rh, sb + 16384 + off); \
                ldsm4(rl, sb + 24576 + off); \
                bh[nb*2][0] = rh[0]; bh[nb*2][1] = rh[1]; \
                bh[nb*2+1][0] = rh[2]; bh[nb*2+1][1] = rh[3]; \
                bl[nb*2][0] = rl[0]; bl[nb*2][1] = rl[1]; \
                bl[nb*2+1][0] = rl[2]; bl[nb*2+1][1] = rl[3]; \
            } \
            _Pragma("unroll") for (int mi = 0; mi < 2; mi++) \
            _Pragma("unroll") for (int ni = 0; ni < 4; ni++) { \
                mma16816(c[mi][half * 4 + ni], ah[mi], bh[ni]); \
                mma16816(c[mi][half * 4 + ni], ah[mi], bl[ni]); \
                mma16816(c[mi][half * 4 + ni], al[mi], bh[ni]); \
            } \
        } \
    }

#define ISSUE_K32(Ahp, Alp, Bhp, Blp, m0, j0, k0, s) \
    { \
        uint32_t so = sb + (uint32_t)(s) * STAGE_BYTES; \
        _Pragma("unroll") for (int i = 0; i < 2; i++) { \
            int e = i * 256 + t, r = e >> 2, q = e & 3; \
            uint32_t off = SWX64(r, q * 16); \
            cpa16(so + off,         &(Ahp)[(size_t)((m0) + r) * 256 + (k0) + q * 8]); \
            cpa16(so + 8192 + off,  &(Alp)[(size_t)((m0) + r) * 256 + (k0) + q * 8]); \
            cpa16(so + 16384 + off, &(Bhp)[(size_t)((j0) + r) * 256 + (k0) + q * 8]); \
            cpa16(so + 24576 + off, &(Blp)[(size_t)((j0) + r) * 256 + (k0) + q * 8]); \
        } \
    }

// single-barrier 3-stage pipeline, issue-before-compute:
// wait -> bar -> issue(ch+2) -> compute(ch) -> commit.
// Overwrite of stage (ch+2)%3 == (ch-1)%3 is safe: every warp passed this
// iteration's barrier only after finishing compute(ch-1).
#define PIPELINE3(NC, ISSUE_CH) \
    ISSUE_CH(0, 0); \
    CP_COMMIT(); \
    ISSUE_CH(1, 1); \
    CP_COMMIT(); \
    for (int ch = 0; ch < (NC); ch++) { \
        CP_WAIT1(); \
        __syncthreads(); \
        if (ch + 2 < (NC)) { ISSUE_CH(ch + 2, (ch + 2) % 3); } \
        GEMM_COMPUTE_CHUNK32((uint32_t)(ch % 3) * STAGE_BYTES); \
        CP_COMMIT(); \
    }

// ================= fused projection GEMM (fx + logits, both passes) =================
__global__ __launch_bounds__(256, 2) void proj_mma(const float* __restrict__ bias,
                                                   const float* __restrict__ temperature) {
    GEMM_PROLOG();
    const int m0 = blockIdx.y * 128;
    const bool isfx = blockIdx.x < 4;
    const int j0 = (isfx ? blockIdx.x : blockIdx.x - 4) * 128;
    const __nv_bfloat16* __restrict__ Bh = isfx ? d_wfx_h : d_wls_h;
    const __nv_bfloat16* __restrict__ Bl = isfx ? d_wfx_l : d_wls_l;
#define PJ_ISSUE(ch, s) ISSUE_K32(d_xs_h, d_xs_l, Bh, Bl, m0, j0, (ch) * 32, s)
    PIPELINE3(8, PJ_ISSUE);
#undef PJ_ISSUE
    if (isfx) {
#pragma unroll
        for (int mi = 0; mi < 2; mi++) {
            int row0 = m0 + wm + mi * 16 + g;
#pragma unroll
            for (int ni = 0; ni < 8; ni++) {
                int col = j0 + wn + ni * 8 + tq * 2;
                float2 bb = *(const float2*)&bias[col];
                uint32_t hh, ll;
                split2(c[mi][ni][0] + bb.x, c[mi][ni][1] + bb.y, hh, ll);
                *(uint32_t*)&d_fx_h[(size_t)row0 * 512 + col] = hh;
                *(uint32_t*)&d_fx_l[(size_t)row0 * 512 + col] = ll;
                split2(c[mi][ni][2] + bb.x, c[mi][ni][3] + bb.y, hh, ll);
                *(uint32_t*)&d_fx_h[(size_t)(row0 + 8) * 512 + col] = hh;
                *(uint32_t*)&d_fx_l[(size_t)(row0 + 8) * 512 + col] = ll;
            }
        }
    } else {
        const int h = (j0 >> 6) + (w >> 2);
        float tp = temperature[h];
        tp = fminf(fmaxf(tp, 0.1f), 5.0f);
        const float invt = 1.f / tp;
        float2 blv[8];
#pragma unroll
        for (int ni = 0; ni < 8; ni++)
            blv[ni] = *(const float2*)&d_bls[j0 + wn + ni * 8 + tq * 2];
#pragma unroll
        for (int mi = 0; mi < 2; mi++)
#pragma unroll
            for (int ni = 0; ni < 8; ni++) {
                c[mi][ni][0] = (c[mi][ni][0] + blv[ni].x) * invt;
                c[mi][ni][1] = (c[mi][ni][1] + blv[ni].y) * invt;
                c[mi][ni][2] = (c[mi][ni][2] + blv[ni].x) * invt;
                c[mi][ni][3] = (c[mi][ni][3] + blv[ni].y) * invt;
            }
#pragma unroll
        for (int mi = 0; mi < 2; mi++)
#pragma unroll
            for (int half = 0; half < 2; half++) {
                const int ci = half * 2;
                float mx = -1e30f;
#pragma unroll
                for (int ni = 0; ni < 8; ni++)
                    mx = fmaxf(mx, fmaxf(c[mi][ni][ci], c[mi][ni][ci + 1]));
                mx = fmaxf(mx, __shfl_xor_sync(0xffffffffu, mx, 1));
                mx = fmaxf(mx, __shfl_xor_sync(0xffffffffu, mx, 2));
                float s = 0.f;
#pragma unroll
                for (int ni = 0; ni < 8; ni++) {
                    float e0 = __expf(c[mi][ni][ci] - mx);
                    float e1 = __expf(c[mi][ni][ci + 1] - mx);
                    c[mi][ni][ci] = e0; c[mi][ni][ci + 1] = e1;
                    s += e0 + e1;
                }
                s += __shfl_xor_sync(0xffffffffu, s, 1);
                s += __shfl_xor_sync(0xffffffffu, s, 2);
                float inv = 1.f / s;
                int row = m0 + wm + mi * 16 + half * 8 + g;
                int pass = row >> 17;
                int rr = row & (ROWS_ - 1);
                int b = rr >> 15, n = rr & (N_ - 1);
                size_t base = (size_t)pass * PASS_SW + ((size_t)(b * H_ + h) * N_ + n) * 64;
#pragma unroll
                for (int ni = 0; ni < 8; ni++) {
                    size_t idx = base + ni * 8 + tq * 2;
                    uint32_t hh, ll;
                    split2(c[mi][ni][ci] * inv, c[mi][ni][ci + 1] * inv, hh, ll);
                    *(uint32_t*)&d_sw_h[idx] = hh;
                    *(uint32_t*)&d_sw_l[idx] = ll;
                }
            }
    }
}

// ================= GEMM 3: out[b] = sw_x[b] (N x 512) @ wot[b] (512 x 256) + bo =================
__global__ __launch_bounds__(256, 2) void final_mma(const float* __restrict__ bo,
                                                    float* __restrict__ out) {
    GEMM_PROLOG();
    const int m0 = blockIdx.y * 128;
    const int j0 = blockIdx.x * 128;
    const int bb_ = m0 >> 15;
    const int n0 = m0 & (N_ - 1);
#define FN_ISSUE(ch, s) \
    { \
        uint32_t so = sb + (uint32_t)(s) * STAGE_BYTES; \
        const int hh_ = (ch) >> 1, g0_ = ((ch) & 1) * 32; \
        const int k0 = (ch) * 32; \
        _Pragma("unroll") for (int i = 0; i < 2; i++) { \
            int e = i * 256 + t, r = e >> 2, q = e & 3; \
            uint32_t off = SWX64(r, q * 16); \
            size_t aidx = ((size_t)(bb_ * H_ + hh_) * N_ + n0 + r) * 64 + g0_ + q * 8; \
            cpa16(so + off,         &d_sw_h[aidx]); \
            cpa16(so + 8192 + off,  &d_sw_l[aidx]); \
            size_t bidx = ((size_t)bb_ * 256 + j0 + r) * 512 + k0 + q * 8; \
            cpa16(so + 16384 + off, &d_wot_h[bidx]); \
            cpa16(so + 24576 + off, &d_wot_l[bidx]); \
        } \
    }
    PIPELINE3(16, FN_ISSUE);
#undef FN_ISSUE
#pragma unroll
    for (int mi = 0; mi < 2; mi++) {
        int row0 = m0 + wm + mi * 16 + g;
#pragma unroll
        for (int ni = 0; ni < 8; ni++) {
            int col = j0 + wn + ni * 8 + tq * 2;
            float2 bbv = *(const float2*)&bo[col];
            float2 o0 = { c[mi][ni][0] + bbv.x, c[mi][ni][1] + bbv.y };
            float2 o1 = { c[mi][ni][2] + bbv.x, c[mi][ni][3] + bbv.y };
            *(float2*)&out[(size_t)row0 * 256 + col] = o0;
            *(float2*)&out[(size_t)(row0 + 8) * 256 + col] = o1;
        }
    }
}

// ================= token aggregation via tensor cores (both passes) =================
// colsum from A fragments on warps 0/1. Fragment row layout: regs {0,2} -> row
// lane>>2, regs {1,3} -> row lane>>2+8 (k-low/k-high halves). cs0 sums regs
// {0,2}, cs1 sums regs {1,3}.
#define TOK_STAGE 32768
#define TOK_SMEM  98304
__global__ __launch_bounds__(256, 2) void token_mma() {
    extern __shared__ char smem[];
    const uint32_t sb = smem_u32(smem);
    const int by = blockIdx.y;
    const int pass = by >> 5;
    const int bh = by & 31;
    float* tok = pass ? d_tokc : d_tokx;
    float* cs  = pass ? d_csc  : d_csx;
    const int b = bh >> 3, h = bh & 7;
    const int n0 = blockIdx.x * 1024;
    const int t = threadIdx.x;
    const int w = t >> 5, lane = t & 31;
    const int wg = (w & 1) * 32;
    const int wc = (w >> 1) * 16;
    const int lg = lane >> 3, l8 = lane & 7;

    const int rowA = (lg >> 1) * 8 + l8;
    uint32_t offA[2];
#pragma unroll
    for (int mi = 0; mi < 2; mi++) {
        int goff = wg + mi * 16 + (lg & 1) * 8;
        offA[mi] = rowA * 128 + ((goff * 2) ^ ((rowA & 7) << 4));
    }
    const int rowB = (lg & 1) * 8 + l8;
    const int coff = wc + (lg >> 1) * 8;
    const uint32_t offB = rowB * 128 + ((coff * 2) ^ ((rowB & 7) << 4));

    const bool do_cs = (w < 2);           // warps 0/1 cover g 0..63 (A replicated over wc)
    float cs0[2] = {0.f, 0.f}, cs1[2] = {0.f, 0.f};

    float c[2][2][4];
#pragma unroll
    for (int mi = 0; mi < 2; mi++)
#pragma unroll
        for (int ni = 0; ni < 2; ni++)
#pragma unroll
            for (int q = 0; q < 4; q++) c[mi][ni][q] = 0.f;

    const size_t swoff = (size_t)pass * PASS_SW;
    const size_t fxoff = (size_t)pass * ROWS_ * 512;

#define TOK_ISSUE(ch, s) \
    { \
        uint32_t so = sb + (uint32_t)(s) * TOK_STAGE; \
        const int nn = n0 + (ch) * 64; \
        _Pragma("unroll") for (int i = 0; i < 2; i++) { \
            int e = i * 256 + t, r = e >> 3, q = e & 7; \
            uint32_t off = SWX(r, q * 16); \
            size_t sidx = swoff + ((size_t)bh * N_ + nn + r) * 64 + q * 8; \
            cpa16(so + off,         &d_sw_h[sidx]); \
            cpa16(so + 8192 + off,  &d_sw_l[sidx]); \
            size_t fidx = fxoff + ((size_t)(b * N_ + nn + r)) * 512 + h * 64 + q * 8; \
            cpa16(so + 16384 + off, &d_fx_h[fidx]); \
            cpa16(so + 24576 + off, &d_fx_l[fidx]); \
        } \
    }

    TOK_ISSUE(0, 0);
    CP_COMMIT();
    TOK_ISSUE(1, 1);
    CP_COMMIT();
    for (int ch = 0; ch < 16; ch++) {
        CP_WAIT1();
        __syncthreads();
        if (ch + 2 < 16) { TOK_ISSUE(ch + 2, (ch + 2) % 3); }
        const uint32_t so = (uint32_t)(ch % 3) * TOK_STAGE;
#pragma unroll
        for (int ks = 0; ks < 4; ks++) {
            const uint32_t kso = so + ks * 2048;
            uint32_t ah[2][4], al[2][4], rbh[4], rbl[4];
#pragma unroll
            for (int mi = 0; mi < 2; mi++) {
                ldsm4t(ah[mi], sb + kso + offA[mi]);
                ldsm4t(al[mi], sb + 8192 + kso + offA[mi]);
            }
            if (do_cs) {
#pragma unroll
                for (int mi = 0; mi < 2; mi++) {
                    cs0[mi] += sum2bf(ah[mi][0]) + sum2bf(ah[mi][2])
                             + sum2bf(al[mi][0]) + sum2bf(al[mi][2]);
                    cs1[mi] += sum2bf(ah[mi][1]) + sum2bf(ah[mi][3])
                             + sum2bf(al[mi][1]) + sum2bf(al[mi][3]);
                }
            }
            ldsm4t(rbh, sb + 16384 + kso + offB);
            ldsm4t(rbl, sb + 24576 + kso + offB);
            uint32_t bfh[2][2] = {{rbh[0], rbh[1]}, {rbh[2], rbh[3]}};
            uint32_t bfl[2][2] = {{rbl[0], rbl[1]}, {rbl[2], rbl[3]}};
#pragma unroll
            for (int mi = 0; mi < 2; mi++)
#pragma unroll
                for (int ni = 0; ni < 2; ni++) {
                    mma16816(c[mi][ni], ah[mi], bfh[ni]);
                    mma16816(c[mi][ni], ah[mi], bfl[ni]);
                    mma16816(c[mi][ni], al[mi], bfh[ni]);
                }
        }
        CP_COMMIT();
    }
#undef TOK_ISSUE
    const int grow = lane >> 2, cpair = (lane & 3) * 2;
#pragma unroll
    for (int mi = 0; mi < 2; mi++) {
        int gg = wg + mi * 16 + grow;
#pragma unroll
        for (int ni = 0; ni < 2; ni++) {
            int col = wc + ni * 8 + cpair;
            atomicAdd(&tok[bh * 4096 + gg * 64 + col],       c[mi][ni][0]);
            atomicAdd(&tok[bh * 4096 + gg * 64 + col + 1],   c[mi][ni][1]);
            atomicAdd(&tok[bh * 4096 + (gg + 8) * 64 + col],     c[mi][ni][2]);
            atomicAdd(&tok[bh * 4096 + (gg + 8) * 64 + col + 1], c[mi][ni][3]);
        }
    }
    if (do_cs) {
#pragma unroll
        for (int mi = 0; mi < 2; mi++) {
            cs0[mi] += __shfl_xor_sync(0xffffffffu, cs0[mi], 1);
            cs0[mi] += __shfl_xor_sync(0xffffffffu, cs0[mi], 2);
            cs1[mi] += __shfl_xor_sync(0xffffffffu, cs1[mi], 1);
            cs1[mi] += __shfl_xor_sync(0xffffffffu, cs1[mi], 2);
            if ((lane & 3) == 0) {
                int gg = wg + mi * 16 + grow;
                atomicAdd(&cs[bh * 64 + gg],     cs0[mi]);
                atomicAdd(&cs[bh * 64 + gg + 8], cs1[mi]);
            }
        }
    }
}

// ================= prep kernels =================
__global__ void presplit2(const float* __restrict__ X0, const float* __restrict__ X1) {
    const int blk = blockIdx.x;
    const float* X = (blk < 32768) ? X0 : X1;
    size_t li = (size_t)(blk & 32767) * 256 + threadIdx.x;
    size_t gi = (size_t)blk * 256 + threadIdx.x;
    float4 v = ((const float4*)X)[li];
    uint2 hh, ll;
    split2(v.x, v.y, hh.x, ll.x);
    split2(v.z, v.w, hh.y, ll.y);
    ((uint2*)d_xs_h)[gi] = hh;
    ((uint2*)d_xs_l)[gi] = ll;
}

// prep_wfx also zeroes token accumulators (grid 512x256 == BH*M*CH)
__global__ void prep_wfx(const float* __restrict__ W) {
    int j = blockIdx.x, cc = threadIdx.x;
    float wv = W[cc * 512 + j];
    __nv_bfloat16 h = __float2bfloat16(wv);
    d_wfx_h[j * 256 + cc] = h;
    d_wfx_l[j * 256 + cc] = __float2bfloat16(wv - __bfloat162float(h));
    int i = j * 256 + cc;
    d_tokx[i] = 0.f; d_tokc[i] = 0.f;
    if (i < BH_ * M_) { d_csx[i] = 0.f; d_csc[i] = 0.f; }
}

__global__ void prep_wls(const float* __restrict__ Wx, const float* __restrict__ Wslice,
                         const float* __restrict__ bx, const float* __restrict__ bslice) {
    extern __shared__ float sm[];
    float* ws = sm;
    float* wx = sm + 64;
    int j = blockIdx.x, h = j >> 6, m = j & 63, t = threadIdx.x;
    if (t < 64) ws[t] = Wslice[t * 64 + m];
    for (int i = t; i < 256 * 16; i += 256) {
        int r = i >> 4, q = i & 15;
        *(float4*)&wx[r * 68 + q * 4] = *(const float4*)&Wx[r * 512 + h * 64 + q * 4];
    }
    __syncthreads();
    float acc = 0.f;
#pragma unroll 8
    for (int e = 0; e < 64; e++) acc += wx[t * 68 + e] * ws[e];
    __nv_bfloat16 hh = __float2bfloat16(acc);
    d_wls_h[j * 256 + t] = hh;
    d_wls_l[j * 256 + t] = __float2bfloat16(acc - __bfloat162float(hh));
    if (t == 0) {
        float bb = bslice[m];
        for (int e = 0; e < 64; e++) bb += bx[h * 64 + e] * ws[e];
        d_bls[j] = bb;
    }
}

// ================= tiny attention + fused Wo refactor =================
__global__ void attn_kernel(const float* __restrict__ Wq,
                            const float* __restrict__ Wk,
                            const float* __restrict__ Wv) {
    extern __shared__ float sm[];
    float* A  = sm;
    float* Ks = sm + 64 * 65;
    float* Vs = Ks + 64 * 64;
    const int bh = blockIdx.x;
    const int g = threadIdx.x;

    for (int idx = g; idx < 4096; idx += 64) {
        int r = idx >> 6, cc = idx & 63;
        A[r * 65 + cc] = d_tokc[bh * 4096 + idx] / (d_csc[bh * 64 + r] + 1e-5f);
    }
    __syncthreads();
    {
        float ka[64], va[64];
#pragma unroll
        for (int cc = 0; cc < 64; cc++) { ka[cc] = 0.f; va[cc] = 0.f; }
        for (int e = 0; e < 64; e++) {
            float te = A[g * 65 + e];
#pragma unroll
            for (int cc = 0; cc < 64; cc++) {
                ka[cc] += te * Wk[e * 64 + cc];
                va[cc] += te * Wv[e * 64 + cc];
            }
        }
#pragma unroll
        for (int cc = 0; cc < 64; cc++) { Ks[g * 64 + cc] = ka[cc]; Vs[g * 64 + cc] = va[cc]; }
    }
    __syncthreads();
    for (int idx = g; idx < 4096; idx += 64) {
        int r = idx >> 6, cc = idx & 63;
        A[r * 65 + cc] = d_tokx[bh * 4096 + idx] / (d_csx[bh * 64 + r] + 1e-5f);
    }
    __syncthreads();

    float q[64];
#pragma unroll
    for (int cc = 0; cc < 64; cc++) q[cc] = 0.f;
    for (int e = 0; e < 64; e++) {
        float te = A[g * 65 + e];
#pragma unroll
        for (int cc = 0; cc < 64; cc++) q[cc] += te * Wq[e * 64 + cc];
    }
    __syncthreads();
    float* srow = &A[g * 65];
    float mx = -1e30f;
    for (int m = 0; m < 64; m++) {
        float a2 = 0.f;
#pragma unroll
        for (int cc = 0; cc < 64; cc++) a2 += q[cc] * Ks[m * 64 + cc];
        a2 *= 0.125f;
        srow[m] = a2;
        mx = fmaxf(mx, a2);
    }
    float sum = 0.f;
    for (int m = 0; m < 64; m++) { float e = __expf(srow[m] - mx); srow[m] = e; sum += e; }
    float inv = 1.f / sum;
    float o[64];
#pragma unroll
    for (int cc = 0; cc < 64; cc++) o[cc] = 0.f;
    for (int m = 0; m < 64; m++) {
        float p = srow[m] * inv;
#pragma unroll
        for (int cc = 0; cc < 64; cc++) o[cc] += p * Vs[m * 64 + cc];
    }
    float invx = 1.f / (d_csx[bh * 64 + g] + 1e-5f);
#pragma unroll
    for (int cc = 0; cc < 64; cc++) d_outsc[bh * 4096 + g * 64 + cc] = o[cc] * invx;
}

// wot + split-transpose fused: writes d_wot_h/l[b][cc][hg] directly
__global__ __launch_bounds__(256) void wot_kernel(const float* __restrict__ Wo) {
    const int bhg = blockIdx.x;
    const int b = bhg >> 9;
    const int hg = bhg & 511;
    const int h = hg >> 6;
    __shared__ float orow[64];
    const int t = threadIdx.x;
    if (t < 64) orow[t] = d_outsc[bhg * 64 + t];
    __syncthreads();
    float acc = 0.f;
#pragma unroll 8
    for (int cc = 0; cc < 64; cc++) acc += orow[cc] * Wo[(h * 64 + cc) * 256 + t];
    __nv_bfloat16 hh = __float2bfloat16(acc);
    d_wot_h[((size_t)b * 256 + t) * 512 + hg] = hh;
    d_wot_l[((size_t)b * 256 + t) * 512 + hg] = __float2bfloat16(acc - __bfloat162float(hh));
}

// ================= launcher =================
extern "C" void kernel_launch(void* const* d_in, const int* in_sizes, int n_in,
                              void* d_out, int out_size) {
    const float* x      = (const float*)d_in[0];
    const float* xc     = (const float*)d_in[1];
    const float* Wfx    = (const float*)d_in[2];
    const float* bfx    = (const float*)d_in[3];
    const float* Wx     = (const float*)d_in[4];
    const float* bx     = (const float*)d_in[5];
    const float* Wslice = (const float*)d_in[6];
    const float* bslice = (const float*)d_in[7];
    const float* temp   = (const float*)d_in[8];
    const float* Wq     = (const float*)d_in[9];
    const float* Wk     = (const float*)d_in[10];
    const float* Wv     = (const float*)d_in[11];
    const float* Wo     = (const float*)d_in[12];
    const float* bo     = (const float*)d_in[13];
    float* out = (float*)d_out;

    const int attn_smem = (64 * 65 + 2 * 64 * 64) * (int)sizeof(float);
    const int wls_smem  = (64 + 256 * 68) * (int)sizeof(float);
    cudaFuncSetAttribute(attn_kernel, cudaFuncAttributeMaxDynamicSharedMemorySize, attn_smem);
    cudaFuncSetAttribute(prep_wls,    cudaFuncAttributeMaxDynamicSharedMemorySize, wls_smem);
    cudaFuncSetAttribute(proj_mma,    cudaFuncAttributeMaxDynamicSharedMemorySize, GEMM_SMEM);
    cudaFuncSetAttribute(final_mma,   cudaFuncAttributeMaxDynamicSharedMemorySize, GEMM_SMEM);
    cudaFuncSetAttribute(token_mma,   cudaFuncAttributeMaxDynamicSharedMemorySize, TOK_SMEM);

    prep_wfx<<<512, 256>>>(Wfx);
    prep_wls<<<512, 256, wls_smem>>>(Wx, Wslice, bx, bslice);
    presplit2<<<65536, 256>>>(x, xc);
    proj_mma<<<dim3(8, 2 * ROWS_ / 128), 256, GEMM_SMEM>>>(bfx, temp);
    token_mma<<<dim3(32, 64), 256, TOK_SMEM>>>();
    attn_kernel<<<BH_, 64, attn_smem>>>(Wq, Wk, Wv);
    wot_kernel<<<B_ * INNER_, 256>>>(Wo);
    final_mma<<<dim3(2, ROWS_ / 128), 256, GEMM_SMEM>>>(bo, out);
}

// round 15
// speedup vs baseline: 1.0330x; 1.0330x over previous
#include <cuda_runtime.h>
#include <cuda_bf16.h>
#include <cstdint>

#define B_ 4
#define N_ 32768
#define C_ 256
#define H_ 8
#define CH_ 64
#define M_ 64
#define INNER_ 512
#define ROWS_ (B_*N_)          // 131072
#define BH_ 32
#define PASS_SW ((size_t)BH_ * N_ * M_)

// ================= static scratch (2 passes: pass0 = x, pass1 = x_cross) =================
__device__ __nv_bfloat16 d_fx_h[(size_t)2 * ROWS_ * 512];
__device__ __nv_bfloat16 d_fx_l[(size_t)2 * ROWS_ * 512];
__device__ __nv_bfloat16 d_sw_h[(size_t)2 * BH_ * N_ * M_];
__device__ __nv_bfloat16 d_sw_l[(size_t)2 * BH_ * N_ * M_];
__device__ __nv_bfloat16 d_xs_h[(size_t)2 * ROWS_ * 256];
__device__ __nv_bfloat16 d_xs_l[(size_t)2 * ROWS_ * 256];
__device__ float d_tokx[BH_ * M_ * CH_];
__device__ float d_tokc[BH_ * M_ * CH_];
__device__ float d_csx[BH_ * M_];
__device__ float d_csc[BH_ * M_];
__device__ float d_outsc[BH_ * M_ * CH_];
__device__ float d_bls[INNER_];
__device__ __nv_bfloat16 d_wfx_h[INNER_ * C_];
__device__ __nv_bfloat16 d_wfx_l[INNER_ * C_];
__device__ __nv_bfloat16 d_wls_h[INNER_ * C_];
__device__ __nv_bfloat16 d_wls_l[INNER_ * C_];
__device__ __nv_bfloat16 d_wot_h[B_ * C_ * INNER_];
__device__ __nv_bfloat16 d_wot_l[B_ * C_ * INNER_];

// ================= helpers =================
__device__ __forceinline__ uint32_t smem_u32(const void* p) {
    uint32_t a;
    asm("{ .reg .u64 t; cvta.to.shared.u64 t, %1; cvt.u32.u64 %0, t; }" : "=r"(a) : "l"(p));
    return a;
}
__device__ __forceinline__ void ldsm4(uint32_t* r, uint32_t addr) {
    asm volatile("ldmatrix.sync.aligned.m8n8.x4.shared.b16 {%0,%1,%2,%3}, [%4];"
                 : "=r"(r[0]), "=r"(r[1]), "=r"(r[2]), "=r"(r[3]) : "r"(addr));
}
__device__ __forceinline__ void ldsm4t(uint32_t* r, uint32_t addr) {
    asm volatile("ldmatrix.sync.aligned.m8n8.x4.trans.shared.b16 {%0,%1,%2,%3}, [%4];"
                 : "=r"(r[0]), "=r"(r[1]), "=r"(r[2]), "=r"(r[3]) : "r"(addr));
}
__device__ __forceinline__ void mma16816(float* c, const uint32_t* a, const uint32_t* b) {
    asm volatile("mma.sync.aligned.m16n8k16.row.col.f32.bf16.bf16.f32 "
                 "{%0,%1,%2,%3}, {%4,%5,%6,%7}, {%8,%9}, {%0,%1,%2,%3};"
                 : "+f"(c[0]), "+f"(c[1]), "+f"(c[2]), "+f"(c[3])
                 : "r"(a[0]), "r"(a[1]), "r"(a[2]), "r"(a[3]), "r"(b[0]), "r"(b[1]));
}
__device__ __forceinline__ void split2(float x, float y, uint32_t& hi, uint32_t& lo) {
    __nv_bfloat16 hx = __float2bfloat16(x), hy = __float2bfloat16(y);
    float rx = x - __bfloat162float(hx), ry = y - __bfloat162float(hy);
    __nv_bfloat16 lx = __float2bfloat16(rx), ly = __float2bfloat16(ry);
    hi = (uint32_t)__bfloat16_as_ushort(hx) | ((uint32_t)__bfloat16_as_ushort(hy) << 16);
    lo = (uint32_t)__bfloat16_as_ushort(lx) | ((uint32_t)__bfloat16_as_ushort(ly) << 16);
}
__device__ __forceinline__ float sum2bf(uint32_t r) {
    __nv_bfloat162 v = *reinterpret_cast<__nv_bfloat162*>(&r);
    return __bfloat162float(v.x) + __bfloat162float(v.y);
}
__device__ __forceinline__ void cpa16(uint32_t dst, const void* src) {
    asm volatile("cp.async.cg.shared.global [%0], [%1], 16;" :: "r"(dst), "l"(src));
}
#define CP_COMMIT() asm volatile("cp.async.commit_group;" ::: "memory")
#define CP_WAIT1()  asm volatile("cp.async.wait_group 1;" ::: "memory")

#define STAGE_BYTES 32768
#define GEMM_SMEM   98304
#define SWX64(r, byte) ((uint32_t)((r) * 64 + ((byte) ^ ((((r) >> 1) & 3) << 4))))
#define SWX(r, byte) ((uint32_t)((r) * 128 + ((byte) ^ (((r) & 7) << 4))))

#define GEMM_PROLOG() \
    extern __shared__ char smem[]; \
    const uint32_t sb = smem_u32(smem); \
    const int t = threadIdx.x; \
    const int w = t >> 5, lane = t & 31; \
    const int wm = (w & 3) * 32, wn = (w >> 2) * 64; \
    const int g = lane >> 2, tq = lane & 3; \
    const int ar_ = lane & 15, akh_ = lane >> 4; \
    const int qd_ = lane >> 3, bl8_ = lane & 7; \
    uint32_t abase[2], axr[2], bbase[4], bxr[4]; \
    _Pragma("unroll") for (int mi = 0; mi < 2; mi++) { \
        int row = wm + mi * 16 + ar_; \
        abase[mi] = row * 64; axr[mi] = ((row >> 1) & 3) << 4; \
    } \
    _Pragma("unroll") for (int nb = 0; nb < 4; nb++) { \
        int row = wn + nb * 16 + (qd_ >> 1) * 8 + bl8_; \
        bbase[nb] = row * 64; bxr[nb] = ((row >> 1) & 3) << 4; \
    } \
    const uint32_t bk16_ = (qd_ & 1) * 16; \
    const uint32_t ak16_ = akh_ * 16; \
    float c[2][8][4]; \
    _Pragma("unroll") for (int mi = 0; mi < 2; mi++) \
    _Pragma("unroll") for (int ni = 0; ni < 8; ni++) \
    _Pragma("unroll") for (int q = 0; q < 4; q++) c[mi][ni][q] = 0.f;

#define GEMM_COMPUTE_CHUNK32(soff) \
    _Pragma("unroll") for (int ks = 0; ks < 2; ks++) { \
        uint32_t ah[2][4], al[2][4]; \
        const uint32_t ka = ks * 32 + ak16_; \
        const uint32_t kb = ks * 32 + bk16_; \
        _Pragma("unroll") for (int mi = 0; mi < 2; mi++) { \
            uint32_t off = (soff) + abase[mi] + (ka ^ axr[mi]); \
            ldsm4(ah[mi], sb + off); \
            ldsm4(al[mi], sb + 8192 + off); \
        } \
        _Pragma("unroll") for (int half = 0; half < 2; half++) { \
            uint32_t bh[4][2], bl[4][2]; \
            _Pragma("unroll") for (int nb = 0; nb < 2; nb++) { \
                uint32_t off = (soff) + bbase[half * 2 + nb] + (kb ^ bxr[half * 2 + nb]); \
                uint32_t rh[4], rl[4]; \
                ldsm4(rh, sb + 16384 + off); \
                ldsm4(rl, sb + 24576 + off); \
                bh[nb*2][0] = rh[0]; bh[nb*2][1] = rh[1]; \
                bh[nb*2+1][0] = rh[2]; bh[nb*2+1][1] = rh[3]; \
                bl[nb*2][0] = rl[0]; bl[nb*2][1] = rl[1]; \
                bl[nb*2+1][0] = rl[2]; bl[nb*2+1][1] = rl[3]; \
            } \
            _Pragma("unroll") for (int mi = 0; mi < 2; mi++) \
            _Pragma("unroll") for (int ni = 0; ni < 4; ni++) { \
                mma16816(c[mi][half * 4 + ni], ah[mi], bh[ni]); \
                mma16816(c[mi][half * 4 + ni], ah[mi], bl[ni]); \
                mma16816(c[mi][half * 4 + ni], al[mi], bh[ni]); \
            } \
        } \
    }

#define ISSUE_K32(Ahp, Alp, Bhp, Blp, m0, j0, k0, s) \
    { \
        uint32_t so = sb + (uint32_t)(s) * STAGE_BYTES; \
        _Pragma("unroll") for (int i = 0; i < 2; i++) { \
            int e = i * 256 + t, r = e >> 2, q = e & 3; \
            uint32_t off = SWX64(r, q * 16); \
            cpa16(so + off,         &(Ahp)[(size_t)((m0) + r) * 256 + (k0) + q * 8]); \
            cpa16(so + 8192 + off,  &(Alp)[(size_t)((m0) + r) * 256 + (k0) + q * 8]); \
            cpa16(so + 16384 + off, &(Bhp)[(size_t)((j0) + r) * 256 + (k0) + q * 8]); \
            cpa16(so + 24576 + off, &(Blp)[(size_t)((j0) + r) * 256 + (k0) + q * 8]); \
        } \
    }

// single-barrier 3-stage pipeline, compute-then-issue (R8 ordering — measured
// faster at occ 2 than issue-first; cross-CTA overlap covers cp.async flight):
// wait -> bar -> compute(ch) -> issue(ch+2) -> commit.
#define PIPELINE3(NC, ISSUE_CH) \
    ISSUE_CH(0, 0); \
    CP_COMMIT(); \
    ISSUE_CH(1, 1); \
    CP_COMMIT(); \
    for (int ch = 0; ch < (NC); ch++) { \
        CP_WAIT1(); \
        __syncthreads(); \
        GEMM_COMPUTE_CHUNK32((uint32_t)(ch % 3) * STAGE_BYTES); \
        if (ch + 2 < (NC)) { ISSUE_CH(ch + 2, (ch + 2) % 3); } \
        CP_COMMIT(); \
    }

// ================= fused projection GEMM (fx + logits, both passes) =================
__global__ __launch_bounds__(256, 2) void proj_mma(const float* __restrict__ bias,
                                                   const float* __restrict__ temperature) {
    GEMM_PROLOG();
    const int m0 = blockIdx.y * 128;
    const bool isfx = blockIdx.x < 4;
    const int j0 = (isfx ? blockIdx.x : blockIdx.x - 4) * 128;
    const __nv_bfloat16* __restrict__ Bh = isfx ? d_wfx_h : d_wls_h;
    const __nv_bfloat16* __restrict__ Bl = isfx ? d_wfx_l : d_wls_l;
#define PJ_ISSUE(ch, s) ISSUE_K32(d_xs_h, d_xs_l, Bh, Bl, m0, j0, (ch) * 32, s)
    PIPELINE3(8, PJ_ISSUE);
#undef PJ_ISSUE
    if (isfx) {
#pragma unroll
        for (int mi = 0; mi < 2; mi++) {
            int row0 = m0 + wm + mi * 16 + g;
#pragma unroll
            for (int ni = 0; ni < 8; ni++) {
                int col = j0 + wn + ni * 8 + tq * 2;
                float2 bb = *(const float2*)&bias[col];
                uint32_t hh, ll;
                split2(c[mi][ni][0] + bb.x, c[mi][ni][1] + bb.y, hh, ll);
                *(uint32_t*)&d_fx_h[(size_t)row0 * 512 + col] = hh;
                *(uint32_t*)&d_fx_l[(size_t)row0 * 512 + col] = ll;
                split2(c[mi][ni][2] + bb.x, c[mi][ni][3] + bb.y, hh, ll);
                *(uint32_t*)&d_fx_h[(size_t)(row0 + 8) * 512 + col] = hh;
                *(uint32_t*)&d_fx_l[(size_t)(row0 + 8) * 512 + col] = ll;
            }
        }
    } else {
        const int h = (j0 >> 6) + (w >> 2);
        float tp = temperature[h];
        tp = fminf(fmaxf(tp, 0.1f), 5.0f);
        const float invt = 1.f / tp;
        float2 blv[8];
#pragma unroll
        for (int ni = 0; ni < 8; ni++)
            blv[ni] = *(const float2*)&d_bls[j0 + wn + ni * 8 + tq * 2];
#pragma unroll
        for (int mi = 0; mi < 2; mi++)
#pragma unroll
            for (int ni = 0; ni < 8; ni++) {
                c[mi][ni][0] = (c[mi][ni][0] + blv[ni].x) * invt;
                c[mi][ni][1] = (c[mi][ni][1] + blv[ni].y) * invt;
                c[mi][ni][2] = (c[mi][ni][2] + blv[ni].x) * invt;
                c[mi][ni][3] = (c[mi][ni][3] + blv[ni].y) * invt;
            }
#pragma unroll
        for (int mi = 0; mi < 2; mi++)
#pragma unroll
            for (int half = 0; half < 2; half++) {
                const int ci = half * 2;
                float mx = -1e30f;
#pragma unroll
                for (int ni = 0; ni < 8; ni++)
                    mx = fmaxf(mx, fmaxf(c[mi][ni][ci], c[mi][ni][ci + 1]));
                mx = fmaxf(mx, __shfl_xor_sync(0xffffffffu, mx, 1));
                mx = fmaxf(mx, __shfl_xor_sync(0xffffffffu, mx, 2));
                float s = 0.f;
#pragma unroll
                for (int ni = 0; ni < 8; ni++) {
                    float e0 = __expf(c[mi][ni][ci] - mx);
                    float e1 = __expf(c[mi][ni][ci + 1] - mx);
                    c[mi][ni][ci] = e0; c[mi][ni][ci + 1] = e1;
                    s += e0 + e1;
                }
                s += __shfl_xor_sync(0xffffffffu, s, 1);
                s += __shfl_xor_sync(0xffffffffu, s, 2);
                float inv = 1.f / s;
                int row = m0 + wm + mi * 16 + half * 8 + g;
                int pass = row >> 17;
                int rr = row & (ROWS_ - 1);
                int b = rr >> 15, n = rr & (N_ - 1);
                size_t base = (size_t)pass * PASS_SW + ((size_t)(b * H_ + h) * N_ + n) * 64;
#pragma unroll
                for (int ni = 0; ni < 8; ni++) {
                    size_t idx = base + ni * 8 + tq * 2;
                    uint32_t hh, ll;
                    split2(c[mi][ni][ci] * inv, c[mi][ni][ci + 1] * inv, hh, ll);
                    *(uint32_t*)&d_sw_h[idx] = hh;
                    *(uint32_t*)&d_sw_l[idx] = ll;
                }
            }
    }
}

// ================= GEMM 3: out[b] = sw_x[b] (N x 512) @ wot[b] (512 x 256) + bo =================
__global__ __launch_bounds__(256, 2) void final_mma(const float* __restrict__ bo,
                                                    float* __restrict__ out) {
    GEMM_PROLOG();
    const int m0 = blockIdx.y * 128;
    const int j0 = blockIdx.x * 128;
    const int bb_ = m0 >> 15;
    const int n0 = m0 & (N_ - 1);
#define FN_ISSUE(ch, s) \
    { \
        uint32_t so = sb + (uint32_t)(s) * STAGE_BYTES; \
        const int hh_ = (ch) >> 1, g0_ = ((ch) & 1) * 32; \
        const int k0 = (ch) * 32; \
        _Pragma("unroll") for (int i = 0; i < 2; i++) { \
            int e = i * 256 + t, r = e >> 2, q = e & 3; \
            uint32_t off = SWX64(r, q * 16); \
            size_t aidx = ((size_t)(bb_ * H_ + hh_) * N_ + n0 + r) * 64 + g0_ + q * 8; \
            cpa16(so + off,         &d_sw_h[aidx]); \
            cpa16(so + 8192 + off,  &d_sw_l[aidx]); \
            size_t bidx = ((size_t)bb_ * 256 + j0 + r) * 512 + k0 + q * 8; \
            cpa16(so + 16384 + off, &d_wot_h[bidx]); \
            cpa16(so + 24576 + off, &d_wot_l[bidx]); \
        } \
    }
    PIPELINE3(16, FN_ISSUE);
#undef FN_ISSUE
#pragma unroll
    for (int mi = 0; mi < 2; mi++) {
        int row0 = m0 + wm + mi * 16 + g;
#pragma unroll
        for (int ni = 0; ni < 8; ni++) {
            int col = j0 + wn + ni * 8 + tq * 2;
            float2 bbv = *(const float2*)&bo[col];
            float2 o0 = { c[mi][ni][0] + bbv.x, c[mi][ni][1] + bbv.y };
            float2 o1 = { c[mi][ni][2] + bbv.x, c[mi][ni][3] + bbv.y };
            *(float2*)&out[(size_t)row0 * 256 + col] = o0;
            *(float2*)&out[(size_t)(row0 + 8) * 256 + col] = o1;
        }
    }
}

// ================= token aggregation via tensor cores (both passes) =================
// Fragment-register colsum on warps 0/1 (A tiles replicated over wc groups).
// Fragment row map: regs {0,2} -> row lane>>2, regs {1,3} -> row lane>>2+8.
#define TOK_STAGE 32768
#define TOK_SMEM  98304
__global__ __launch_bounds__(256, 2) void token_mma() {
    extern __shared__ char smem[];
    const uint32_t sb = smem_u32(smem);
    const int by = blockIdx.y;
    const int pass = by >> 5;
    const int bh = by & 31;
    float* tok = pass ? d_tokc : d_tokx;
    float* cs  = pass ? d_csc  : d_csx;
    const int b = bh >> 3, h = bh & 7;
    const int n0 = blockIdx.x * 1024;
    const int t = threadIdx.x;
    const int w = t >> 5, lane = t & 31;
    const int wg = (w & 1) * 32;
    const int wc = (w >> 1) * 16;
    const int lg = lane >> 3, l8 = lane & 7;

    const int rowA = (lg >> 1) * 8 + l8;
    uint32_t offA[2];
#pragma unroll
    for (int mi = 0; mi < 2; mi++) {
        int goff = wg + mi * 16 + (lg & 1) * 8;
        offA[mi] = rowA * 128 + ((goff * 2) ^ ((rowA & 7) << 4));
    }
    const int rowB = (lg & 1) * 8 + l8;
    const int coff = wc + (lg >> 1) * 8;
    const uint32_t offB = rowB * 128 + ((coff * 2) ^ ((rowB & 7) << 4));

    const bool do_cs = (w < 2);
    float cs0[2] = {0.f, 0.f}, cs1[2] = {0.f, 0.f};

    float c[2][2][4];
#pragma unroll
    for (int mi = 0; mi < 2; mi++)
#pragma unroll
        for (int ni = 0; ni < 2; ni++)
#pragma unroll
            for (int q = 0; q < 4; q++) c[mi][ni][q] = 0.f;

    const size_t swoff = (size_t)pass * PASS_SW;
    const size_t fxoff = (size_t)pass * ROWS_ * 512;

#define TOK_ISSUE(ch, s) \
    { \
        uint32_t so = sb + (uint32_t)(s) * TOK_STAGE; \
        const int nn = n0 + (ch) * 64; \
        _Pragma("unroll") for (int i = 0; i < 2; i++) { \
            int e = i * 256 + t, r = e >> 3, q = e & 7; \
            uint32_t off = SWX(r, q * 16); \
            size_t sidx = swoff + ((size_t)bh * N_ + nn + r) * 64 + q * 8; \
            cpa16(so + off,         &d_sw_h[sidx]); \
            cpa16(so + 8192 + off,  &d_sw_l[sidx]); \
            size_t fidx = fxoff + ((size_t)(b * N_ + nn + r)) * 512 + h * 64 + q * 8; \
            cpa16(so + 16384 + off, &d_fx_h[fidx]); \
            cpa16(so + 24576 + off, &d_fx_l[fidx]); \
        } \
    }

    TOK_ISSUE(0, 0);
    CP_COMMIT();
    TOK_ISSUE(1, 1);
    CP_COMMIT();
    for (int ch = 0; ch < 16; ch++) {
        CP_WAIT1();
        __syncthreads();
        const uint32_t so = (uint32_t)(ch % 3) * TOK_STAGE;
#pragma unroll
        for (int ks = 0; ks < 4; ks++) {
            const uint32_t kso = so + ks * 2048;
            uint32_t ah[2][4], al[2][4], rbh[4], rbl[4];
#pragma unroll
            for (int mi = 0; mi < 2; mi++) {
                ldsm4t(ah[mi], sb + kso + offA[mi]);
                ldsm4t(al[mi], sb + 8192 + kso + offA[mi]);
            }
            if (do_cs) {
#pragma unroll
                for (int mi = 0; mi < 2; mi++) {
                    cs0[mi] += sum2bf(ah[mi][0]) + sum2bf(ah[mi][2])
                             + sum2bf(al[mi][0]) + sum2bf(al[mi][2]);
                    cs1[mi] += sum2bf(ah[mi][1]) + sum2bf(ah[mi][3])
                             + sum2bf(al[mi][1]) + sum2bf(al[mi][3]);
                }
            }
            ldsm4t(rbh, sb + 16384 + kso + offB);
            ldsm4t(rbl, sb + 24576 + kso + offB);
            uint32_t bfh[2][2] = {{rbh[0], rbh[1]}, {rbh[2], rbh[3]}};
            uint32_t bfl[2][2] = {{rbl[0], rbl[1]}, {rbl[2], rbl[3]}};
#pragma unroll
            for (int mi = 0; mi < 2; mi++)
#pragma unroll
                for (int ni = 0; ni < 2; ni++) {
                    mma16816(c[mi][ni], ah[mi], bfh[ni]);
                    mma16816(c[mi][ni], ah[mi], bfl[ni]);
                    mma16816(c[mi][ni], al[mi], bfh[ni]);
                }
        }
        if (ch + 2 < 16) { TOK_ISSUE(ch + 2, (ch + 2) % 3); }
        CP_COMMIT();
    }
#undef TOK_ISSUE
    const int grow = lane >> 2, cpair = (lane & 3) * 2;
#pragma unroll
    for (int mi = 0; mi < 2; mi++) {
        int gg = wg + mi * 16 + grow;
#pragma unroll
        for (int ni = 0; ni < 2; ni++) {
            int col = wc + ni * 8 + cpair;
            atomicAdd(&tok[bh * 4096 + gg * 64 + col],       c[mi][ni][0]);
            atomicAdd(&tok[bh * 4096 + gg * 64 + col + 1],   c[mi][ni][1]);
            atomicAdd(&tok[bh * 4096 + (gg + 8) * 64 + col],     c[mi][ni][2]);
            atomicAdd(&tok[bh * 4096 + (gg + 8) * 64 + col + 1], c[mi][ni][3]);
        }
    }
    if (do_cs) {
#pragma unroll
        for (int mi = 0; mi < 2; mi++) {
            cs0[mi] += __shfl_xor_sync(0xffffffffu, cs0[mi], 1);
            cs0[mi] += __shfl_xor_sync(0xffffffffu, cs0[mi], 2);
            cs1[mi] += __shfl_xor_sync(0xffffffffu, cs1[mi], 1);
            cs1[mi] += __shfl_xor_sync(0xffffffffu, cs1[mi], 2);
            if ((lane & 3) == 0) {
                int gg = wg + mi * 16 + grow;
                atomicAdd(&cs[bh * 64 + gg],     cs0[mi]);
                atomicAdd(&cs[bh * 64 + gg + 8], cs1[mi]);
            }
        }
    }
}

// ================= prep kernels =================
__global__ void presplit2(const float* __restrict__ X0, const float* __restrict__ X1) {
    const int blk = blockIdx.x;
    const float* X = (blk < 32768) ? X0 : X1;
    size_t li = (size_t)(blk & 32767) * 256 + threadIdx.x;
    size_t gi = (size_t)blk * 256 + threadIdx.x;
    float4 v = ((const float4*)X)[li];
    uint2 hh, ll;
    split2(v.x, v.y, hh.x, ll.x);
    split2(v.z, v.w, hh.y, ll.y);
    ((uint2*)d_xs_h)[gi] = hh;
    ((uint2*)d_xs_l)[gi] = ll;
}

// prep_wfx also zeroes token accumulators (grid 512x256 == BH*M*CH)
__global__ void prep_wfx(const float* __restrict__ W) {
    int j = blockIdx.x, cc = threadIdx.x;
    float wv = W[cc * 512 + j];
    __nv_bfloat16 h = __float2bfloat16(wv);
    d_wfx_h[j * 256 + cc] = h;
    d_wfx_l[j * 256 + cc] = __float2bfloat16(wv - __bfloat162float(h));
    int i = j * 256 + cc;
    d_tokx[i] = 0.f; d_tokc[i] = 0.f;
    if (i < BH_ * M_) { d_csx[i] = 0.f; d_csc[i] = 0.f; }
}

__global__ void prep_wls(const float* __restrict__ Wx, const float* __restrict__ Wslice,
                         const float* __restrict__ bx, const float* __restrict__ bslice) {
    extern __shared__ float sm[];
    float* ws = sm;
    float* wx = sm + 64;
    int j = blockIdx.x, h = j >> 6, m = j & 63, t = threadIdx.x;
    if (t < 64) ws[t] = Wslice[t * 64 + m];
    for (int i = t; i < 256 * 16; i += 256) {
        int r = i >> 4, q = i & 15;
        *(float4*)&wx[r * 68 + q * 4] = *(const float4*)&Wx[r * 512 + h * 64 + q * 4];
    }
    __syncthreads();
    float acc = 0.f;
#pragma unroll 8
    for (int e = 0; e < 64; e++) acc += wx[t * 68 + e] * ws[e];
    __nv_bfloat16 hh = __float2bfloat16(acc);
    d_wls_h[j * 256 + t] = hh;
    d_wls_l[j * 256 + t] = __float2bfloat16(acc - __bfloat162float(hh));
    if (t == 0) {
        float bb = bslice[m];
        for (int e = 0; e < 64; e++) bb += bx[h * 64 + e] * ws[e];
        d_bls[j] = bb;
    }
}

// ================= tiny attention + fused Wo refactor =================
__global__ void attn_kernel(const float* __restrict__ Wq,
                            const float* __restrict__ Wk,
                            const float* __restrict__ Wv) {
    extern __shared__ float sm[];
    float* A  = sm;
    float* Ks = sm + 64 * 65;
    float* Vs = Ks + 64 * 64;
    const int bh = blockIdx.x;
    const int g = threadIdx.x;

    for (int idx = g; idx < 4096; idx += 64) {
        int r = idx >> 6, cc = idx & 63;
        A[r * 65 + cc] = d_tokc[bh * 4096 + idx] / (d_csc[bh * 64 + r] + 1e-5f);
    }
    __syncthreads();
    {
        float ka[64], va[64];
#pragma unroll
        for (int cc = 0; cc < 64; cc++) { ka[cc] = 0.f; va[cc] = 0.f; }
        for (int e = 0; e < 64; e++) {
            float te = A[g * 65 + e];
#pragma unroll
            for (int cc = 0; cc < 64; cc++) {
                ka[cc] += te * Wk[e * 64 + cc];
                va[cc] += te * Wv[e * 64 + cc];
            }
        }
#pragma unroll
        for (int cc = 0; cc < 64; cc++) { Ks[g * 64 + cc] = ka[cc]; Vs[g * 64 + cc] = va[cc]; }
    }
    __syncthreads();
    for (int idx = g; idx < 4096; idx += 64) {
        int r = idx >> 6, cc = idx & 63;
        A[r * 65 + cc] = d_tokx[bh * 4096 + idx] / (d_csx[bh * 64 + r] + 1e-5f);
    }
    __syncthreads();

    float q[64];
#pragma unroll
    for (int cc = 0; cc < 64; cc++) q[cc] = 0.f;
    for (int e = 0; e < 64; e++) {
        float te = A[g * 65 + e];
#pragma unroll
        for (int cc = 0; cc < 64; cc++) q[cc] += te * Wq[e * 64 + cc];
    }
    __syncthreads();
    float* srow = &A[g * 65];
    float mx = -1e30f;
    for (int m = 0; m < 64; m++) {
        float a2 = 0.f;
#pragma unroll
        for (int cc = 0; cc < 64; cc++) a2 += q[cc] * Ks[m * 64 + cc];
        a2 *= 0.125f;
        srow[m] = a2;
        mx = fmaxf(mx, a2);
    }
    float sum = 0.f;
    for (int m = 0; m < 64; m++) { float e = __expf(srow[m] - mx); srow[m] = e; sum += e; }
    float inv = 1.f / sum;
    float o[64];
#pragma unroll
    for (int cc = 0; cc < 64; cc++) o[cc] = 0.f;
    for (int m = 0; m < 64; m++) {
        float p = srow[m] * inv;
#pragma unroll
        for (int cc = 0; cc < 64; cc++) o[cc] += p * Vs[m * 64 + cc];
    }
    float invx = 1.f / (d_csx[bh * 64 + g] + 1e-5f);
#pragma unroll
    for (int cc = 0; cc < 64; cc++) d_outsc[bh * 4096 + g * 64 + cc] = o[cc] * invx;
}

// wot + split-transpose fused: writes d_wot_h/l[b][cc][hg] directly
__global__ __launch_bounds__(256) void wot_kernel(const float* __restrict__ Wo) {
    const int bhg = blockIdx.x;
    const int b = bhg >> 9;
    const int hg = bhg & 511;
    const int h = hg >> 6;
    __shared__ float orow[64];
    const int t = threadIdx.x;
    if (t < 64) orow[t] = d_outsc[bhg * 64 + t];
    __syncthreads();
    float acc = 0.f;
#pragma unroll 8
    for (int cc = 0; cc < 64; cc++) acc += orow[cc] * Wo[(h * 64 + cc) * 256 + t];
    __nv_bfloat16 hh = __float2bfloat16(acc);
    d_wot_h[((size_t)b * 256 + t) * 512 + hg] = hh;
    d_wot_l[((size_t)b * 256 + t) * 512 + hg] = __float2bfloat16(acc - __bfloat162float(hh));
}

// ================= launcher =================
extern "C" void kernel_launch(void* const* d_in, const int* in_sizes, int n_in,
                              void* d_out, int out_size) {
    const float* x      = (const float*)d_in[0];
    const float* xc     = (const float*)d_in[1];
    const float* Wfx    = (const float*)d_in[2];
    const float* bfx    = (const float*)d_in[3];
    const float* Wx     = (const float*)d_in[4];
    const float* bx     = (const float*)d_in[5];
    const float* Wslice = (const float*)d_in[6];
    const float* bslice = (const float*)d_in[7];
    const float* temp   = (const float*)d_in[8];
    const float* Wq     = (const float*)d_in[9];
    const float* Wk     = (const float*)d_in[10];
    const float* Wv     = (const float*)d_in[11];
    const float* Wo     = (const float*)d_in[12];
    const float* bo     = (const float*)d_in[13];
    float* out = (float*)d_out;

    const int attn_smem = (64 * 65 + 2 * 64 * 64) * (int)sizeof(float);
    const int wls_smem  = (64 + 256 * 68) * (int)sizeof(float);
    cudaFuncSetAttribute(attn_kernel, cudaFuncAttributeMaxDynamicSharedMemorySize, attn_smem);
    cudaFuncSetAttribute(prep_wls,    cudaFuncAttributeMaxDynamicSharedMemorySize, wls_smem);
    cudaFuncSetAttribute(proj_mma,    cudaFuncAttributeMaxDynamicSharedMemorySize, GEMM_SMEM);
    cudaFuncSetAttribute(final_mma,   cudaFuncAttributeMaxDynamicSharedMemorySize, GEMM_SMEM);
    cudaFuncSetAttribute(token_mma,   cudaFuncAttributeMaxDynamicSharedMemorySize, TOK_SMEM);

    prep_wfx<<<512, 256>>>(Wfx);
    prep_wls<<<512, 256, wls_smem>>>(Wx, Wslice, bx, bslice);
    presplit2<<<65536, 256>>>(x, xc);
    proj_mma<<<dim3(8, 2 * ROWS_ / 128), 256, GEMM_SMEM>>>(bfx, temp);
    token_mma<<<dim3(32, 64), 256, TOK_SMEM>>>();
    attn_kernel<<<BH_, 64, attn_smem>>>(Wq, Wk, Wv);
    wot_kernel<<<B_ * INNER_, 256>>>(Wo);
    final_mma<<<dim3(2, ROWS_ / 128), 256, GEMM_SMEM>>>(bo, out);
}

// round 16
// speedup vs baseline: 1.0363x; 1.0032x over previous
#include <cuda_runtime.h>
#include <cuda_bf16.h>
#include <cstdint>

#define B_ 4
#define N_ 32768
#define C_ 256
#define H_ 8
#define CH_ 64
#define M_ 64
#define INNER_ 512
#define ROWS_ (B_*N_)          // 131072
#define BH_ 32
#define PASS_SW ((size_t)BH_ * N_ * M_)

// ================= static scratch (2 passes: pass0 = x, pass1 = x_cross) =================
__device__ __nv_bfloat16 d_fx_h[(size_t)2 * ROWS_ * 512];
__device__ __nv_bfloat16 d_fx_l[(size_t)2 * ROWS_ * 512];
__device__ __nv_bfloat16 d_sw_h[(size_t)2 * BH_ * N_ * M_];
__device__ __nv_bfloat16 d_sw_l[(size_t)2 * BH_ * N_ * M_];
__device__ __nv_bfloat16 d_xs_h[(size_t)2 * ROWS_ * 256];
__device__ __nv_bfloat16 d_xs_l[(size_t)2 * ROWS_ * 256];
__device__ float d_tokx[BH_ * M_ * CH_];
__device__ float d_tokc[BH_ * M_ * CH_];
__device__ float d_csx[BH_ * M_];
__device__ float d_csc[BH_ * M_];
__device__ float d_outsc[BH_ * M_ * CH_];
__device__ float d_bls[INNER_];
__device__ __nv_bfloat16 d_wfx_h[INNER_ * C_];
__device__ __nv_bfloat16 d_wfx_l[INNER_ * C_];
__device__ __nv_bfloat16 d_wls_h[INNER_ * C_];
__device__ __nv_bfloat16 d_wls_l[INNER_ * C_];
__device__ __nv_bfloat16 d_wot_h[B_ * C_ * INNER_];
__device__ __nv_bfloat16 d_wot_l[B_ * C_ * INNER_];

// ================= helpers =================
__device__ __forceinline__ uint32_t smem_u32(const void* p) {
    uint32_t a;
    asm("{ .reg .u64 t; cvta.to.shared.u64 t, %1; cvt.u32.u64 %0, t; }" : "=r"(a) : "l"(p));
    return a;
}
__device__ __forceinline__ void ldsm4(uint32_t* r, uint32_t addr) {
    asm volatile("ldmatrix.sync.aligned.m8n8.x4.shared.b16 {%0,%1,%2,%3}, [%4];"
                 : "=r"(r[0]), "=r"(r[1]), "=r"(r[2]), "=r"(r[3]) : "r"(addr));
}
__device__ __forceinline__ void ldsm4t(uint32_t* r, uint32_t addr) {
    asm volatile("ldmatrix.sync.aligned.m8n8.x4.trans.shared.b16 {%0,%1,%2,%3}, [%4];"
                 : "=r"(r[0]), "=r"(r[1]), "=r"(r[2]), "=r"(r[3]) : "r"(addr));
}
__device__ __forceinline__ void mma16816(float* c, const uint32_t* a, const uint32_t* b) {
    asm volatile("mma.sync.aligned.m16n8k16.row.col.f32.bf16.bf16.f32 "
                 "{%0,%1,%2,%3}, {%4,%5,%6,%7}, {%8,%9}, {%0,%1,%2,%3};"
                 : "+f"(c[0]), "+f"(c[1]), "+f"(c[2]), "+f"(c[3])
                 : "r"(a[0]), "r"(a[1]), "r"(a[2]), "r"(a[3]), "r"(b[0]), "r"(b[1]));
}
__device__ __forceinline__ void split2(float x, float y, uint32_t& hi, uint32_t& lo) {
    __nv_bfloat16 hx = __float2bfloat16(x), hy = __float2bfloat16(y);
    float rx = x - __bfloat162float(hx), ry = y - __bfloat162float(hy);
    __nv_bfloat16 lx = __float2bfloat16(rx), ly = __float2bfloat16(ry);
    hi = (uint32_t)__bfloat16_as_ushort(hx) | ((uint32_t)__bfloat16_as_ushort(hy) << 16);
    lo = (uint32_t)__bfloat16_as_ushort(lx) | ((uint32_t)__bfloat16_as_ushort(ly) << 16);
}
__device__ __forceinline__ float sum2bf(uint32_t r) {
    __nv_bfloat162 v = *reinterpret_cast<__nv_bfloat162*>(&r);
    return __bfloat162float(v.x) + __bfloat162float(v.y);
}
__device__ __forceinline__ void cpa16(uint32_t dst, const void* src) {
    asm volatile("cp.async.cg.shared.global [%0], [%1], 16;" :: "r"(dst), "l"(src));
}
#define CP_COMMIT() asm volatile("cp.async.commit_group;" ::: "memory")
#define CP_WAIT1()  asm volatile("cp.async.wait_group 1;" ::: "memory")

#define STAGE_BYTES 32768
#define GEMM_SMEM   98304
#define SWX64(r, byte) ((uint32_t)((r) * 64 + ((byte) ^ ((((r) >> 1) & 3) << 4))))
#define SWX(r, byte) ((uint32_t)((r) * 128 + ((byte) ^ (((r) & 7) << 4))))

#define GEMM_PROLOG() \
    extern __shared__ char smem[]; \
    const uint32_t sb = smem_u32(smem); \
    const int t = threadIdx.x; \
    const int w = t >> 5, lane = t & 31; \
    const int wm = (w & 3) * 32, wn = (w >> 2) * 64; \
    const int g = lane >> 2, tq = lane & 3; \
    const int ar_ = lane & 15, akh_ = lane >> 4; \
    const int qd_ = lane >> 3, bl8_ = lane & 7; \
    uint32_t abase[2], axr[2], bbase[4], bxr[4]; \
    _Pragma("unroll") for (int mi = 0; mi < 2; mi++) { \
        int row = wm + mi * 16 + ar_; \
        abase[mi] = row * 64; axr[mi] = ((row >> 1) & 3) << 4; \
    } \
    _Pragma("unroll") for (int nb = 0; nb < 4; nb++) { \
        int row = wn + nb * 16 + (qd_ >> 1) * 8 + bl8_; \
        bbase[nb] = row * 64; bxr[nb] = ((row >> 1) & 3) << 4; \
    } \
    const uint32_t bk16_ = (qd_ & 1) * 16; \
    const uint32_t ak16_ = akh_ * 16; \
    float c[2][8][4]; \
    _Pragma("unroll") for (int mi = 0; mi < 2; mi++) \
    _Pragma("unroll") for (int ni = 0; ni < 8; ni++) \
    _Pragma("unroll") for (int q = 0; q < 4; q++) c[mi][ni][q] = 0.f;

#define GEMM_COMPUTE_CHUNK32(soff) \
    _Pragma("unroll") for (int ks = 0; ks < 2; ks++) { \
        uint32_t ah[2][4], al[2][4]; \
        const uint32_t ka = ks * 32 + ak16_; \
        const uint32_t kb = ks * 32 + bk16_; \
        _Pragma("unroll") for (int mi = 0; mi < 2; mi++) { \
            uint32_t off = (soff) + abase[mi] + (ka ^ axr[mi]); \
            ldsm4(ah[mi], sb + off); \
            ldsm4(al[mi], sb + 8192 + off); \
        } \
        _Pragma("unroll") for (int half = 0; half < 2; half++) { \
            uint32_t bh[4][2], bl[4][2]; \
            _Pragma("unroll") for (int nb = 0; nb < 2; nb++) { \
                uint32_t off = (soff) + bbase[half * 2 + nb] + (kb ^ bxr[half * 2 + nb]); \
                uint32_t rh[4], rl[4]; \
                ldsm4(rh, sb + 16384 + off); \
                ldsm4(rl, sb + 24576 + off); \
                bh[nb*2][0] = rh[0]; bh[nb*2][1] = rh[1]; \
                bh[nb*2+1][0] = rh[2]; bh[nb*2+1][1] = rh[3]; \
                bl[nb*2][0] = rl[0]; bl[nb*2][1] = rl[1]; \
                bl[nb*2+1][0] = rl[2]; bl[nb*2+1][1] = rl[3]; \
            } \
            _Pragma("unroll") for (int mi = 0; mi < 2; mi++) \
            _Pragma("unroll") for (int ni = 0; ni < 4; ni++) { \
                mma16816(c[mi][half * 4 + ni], ah[mi], bh[ni]); \
                mma16816(c[mi][half * 4 + ni], ah[mi], bl[ni]); \
                mma16816(c[mi][half * 4 + ni], al[mi], bh[ni]); \
            } \
        } \
    }

#define ISSUE_K32(Ahp, Alp, Bhp, Blp, m0, j0, k0, s) \
    { \
        uint32_t so = sb + (uint32_t)(s) * STAGE_BYTES; \
        _Pragma("unroll") for (int i = 0; i < 2; i++) { \
            int e = i * 256 + t, r = e >> 2, q = e & 3; \
            uint32_t off = SWX64(r, q * 16); \
            cpa16(so + off,         &(Ahp)[(size_t)((m0) + r) * 256 + (k0) + q * 8]); \
            cpa16(so + 8192 + off,  &(Alp)[(size_t)((m0) + r) * 256 + (k0) + q * 8]); \
            cpa16(so + 16384 + off, &(Bhp)[(size_t)((j0) + r) * 256 + (k0) + q * 8]); \
            cpa16(so + 24576 + off, &(Blp)[(size_t)((j0) + r) * 256 + (k0) + q * 8]); \
        } \
    }

// single-barrier 3-stage pipeline, compute-then-issue (measured-best ordering):
// wait -> bar -> compute(ch) -> issue(ch+2) -> commit.
#define PIPELINE3(NC, ISSUE_CH) \
    ISSUE_CH(0, 0); \
    CP_COMMIT(); \
    ISSUE_CH(1, 1); \
    CP_COMMIT(); \
    for (int ch = 0; ch < (NC); ch++) { \
        CP_WAIT1(); \
        __syncthreads(); \
        GEMM_COMPUTE_CHUNK32((uint32_t)(ch % 3) * STAGE_BYTES); \
        if (ch + 2 < (NC)) { ISSUE_CH(ch + 2, (ch + 2) % 3); } \
        CP_COMMIT(); \
    }

// ================= fused projection GEMM (fx + logits, both passes) =================
__global__ __launch_bounds__(256, 2) void proj_mma(const float* __restrict__ bias,
                                                   const float* __restrict__ temperature) {
    GEMM_PROLOG();
    const int m0 = blockIdx.y * 128;
    const bool isfx = blockIdx.x < 4;
    const int j0 = (isfx ? blockIdx.x : blockIdx.x - 4) * 128;
    const __nv_bfloat16* __restrict__ Bh = isfx ? d_wfx_h : d_wls_h;
    const __nv_bfloat16* __restrict__ Bl = isfx ? d_wfx_l : d_wls_l;
#define PJ_ISSUE(ch, s) ISSUE_K32(d_xs_h, d_xs_l, Bh, Bl, m0, j0, (ch) * 32, s)
    PIPELINE3(8, PJ_ISSUE);
#undef PJ_ISSUE
    if (isfx) {
#pragma unroll
        for (int mi = 0; mi < 2; mi++) {
            int row0 = m0 + wm + mi * 16 + g;
#pragma unroll
            for (int ni = 0; ni < 8; ni++) {
                int col = j0 + wn + ni * 8 + tq * 2;
                float2 bb = *(const float2*)&bias[col];
                uint32_t hh, ll;
                split2(c[mi][ni][0] + bb.x, c[mi][ni][1] + bb.y, hh, ll);
                *(uint32_t*)&d_fx_h[(size_t)row0 * 512 + col] = hh;
                *(uint32_t*)&d_fx_l[(size_t)row0 * 512 + col] = ll;
                split2(c[mi][ni][2] + bb.x, c[mi][ni][3] + bb.y, hh, ll);
                *(uint32_t*)&d_fx_h[(size_t)(row0 + 8) * 512 + col] = hh;
                *(uint32_t*)&d_fx_l[(size_t)(row0 + 8) * 512 + col] = ll;
            }
        }
    } else {
        const int h = (j0 >> 6) + (w >> 2);
        float tp = temperature[h];
        tp = fminf(fmaxf(tp, 0.1f), 5.0f);
        const float invt = 1.f / tp;
        float2 blv[8];
#pragma unroll
        for (int ni = 0; ni < 8; ni++)
            blv[ni] = *(const float2*)&d_bls[j0 + wn + ni * 8 + tq * 2];
#pragma unroll
        for (int mi = 0; mi < 2; mi++)
#pragma unroll
            for (int ni = 0; ni < 8; ni++) {
                c[mi][ni][0] = (c[mi][ni][0] + blv[ni].x) * invt;
                c[mi][ni][1] = (c[mi][ni][1] + blv[ni].y) * invt;
                c[mi][ni][2] = (c[mi][ni][2] + blv[ni].x) * invt;
                c[mi][ni][3] = (c[mi][ni][3] + blv[ni].y) * invt;
            }
#pragma unroll
        for (int mi = 0; mi < 2; mi++)
#pragma unroll
            for (int half = 0; half < 2; half++) {
                const int ci = half * 2;
                float mx = -1e30f;
#pragma unroll
                for (int ni = 0; ni < 8; ni++)
                    mx = fmaxf(mx, fmaxf(c[mi][ni][ci], c[mi][ni][ci + 1]));
                mx = fmaxf(mx, __shfl_xor_sync(0xffffffffu, mx, 1));
                mx = fmaxf(mx, __shfl_xor_sync(0xffffffffu, mx, 2));
                float s = 0.f;
#pragma unroll
                for (int ni = 0; ni < 8; ni++) {
                    float e0 = __expf(c[mi][ni][ci] - mx);
                    float e1 = __expf(c[mi][ni][ci + 1] - mx);
                    c[mi][ni][ci] = e0; c[mi][ni][ci + 1] = e1;
                    s += e0 + e1;
                }
                s += __shfl_xor_sync(0xffffffffu, s, 1);
                s += __shfl_xor_sync(0xffffffffu, s, 2);
                float inv = 1.f / s;
                int row = m0 + wm + mi * 16 + half * 8 + g;
                int pass = row >> 17;
                int rr = row & (ROWS_ - 1);
                int b = rr >> 15, n = rr & (N_ - 1);
                size_t base = (size_t)pass * PASS_SW + ((size_t)(b * H_ + h) * N_ + n) * 64;
#pragma unroll
                for (int ni = 0; ni < 8; ni++) {
                    size_t idx = base + ni * 8 + tq * 2;
                    uint32_t hh, ll;
                    split2(c[mi][ni][ci] * inv, c[mi][ni][ci + 1] * inv, hh, ll);
                    *(uint32_t*)&d_sw_h[idx] = hh;
                    *(uint32_t*)&d_sw_l[idx] = ll;
                }
            }
    }
}

// ================= GEMM 3: out[b] = sw_x[b] (N x 512) @ wot[b] (512 x 256) + bo =================
__global__ __launch_bounds__(256, 2) void final_mma(const float* __restrict__ bo,
                                                    float* __restrict__ out) {
    GEMM_PROLOG();
    const int m0 = blockIdx.y * 128;
    const int j0 = blockIdx.x * 128;
    const int bb_ = m0 >> 15;
    const int n0 = m0 & (N_ - 1);
#define FN_ISSUE(ch, s) \
    { \
        uint32_t so = sb + (uint32_t)(s) * STAGE_BYTES; \
        const int hh_ = (ch) >> 1, g0_ = ((ch) & 1) * 32; \
        const int k0 = (ch) * 32; \
        _Pragma("unroll") for (int i = 0; i < 2; i++) { \
            int e = i * 256 + t, r = e >> 2, q = e & 3; \
            uint32_t off = SWX64(r, q * 16); \
            size_t aidx = ((size_t)(bb_ * H_ + hh_) * N_ + n0 + r) * 64 + g0_ + q * 8; \
            cpa16(so + off,         &d_sw_h[aidx]); \
            cpa16(so + 8192 + off,  &d_sw_l[aidx]); \
            size_t bidx = ((size_t)bb_ * 256 + j0 + r) * 512 + k0 + q * 8; \
            cpa16(so + 16384 + off, &d_wot_h[bidx]); \
            cpa16(so + 24576 + off, &d_wot_l[bidx]); \
        } \
    }
    PIPELINE3(16, FN_ISSUE);
#undef FN_ISSUE
#pragma unroll
    for (int mi = 0; mi < 2; mi++) {
        int row0 = m0 + wm + mi * 16 + g;
#pragma unroll
        for (int ni = 0; ni < 8; ni++) {
            int col = j0 + wn + ni * 8 + tq * 2;
            float2 bbv = *(const float2*)&bo[col];
            float2 o0 = { c[mi][ni][0] + bbv.x, c[mi][ni][1] + bbv.y };
            float2 o1 = { c[mi][ni][2] + bbv.x, c[mi][ni][3] + bbv.y };
            *(float2*)&out[(size_t)row0 * 256 + col] = o0;
            *(float2*)&out[(size_t)(row0 + 8) * 256 + col] = o1;
        }
    }
}

// ================= token aggregation via tensor cores (both passes) =================
#define TOK_STAGE 32768
#define TOK_SMEM  98304
__global__ __launch_bounds__(256, 2) void token_mma() {
    extern __shared__ char smem[];
    const uint32_t sb = smem_u32(smem);
    const int by = blockIdx.y;
    const int pass = by >> 5;
    const int bh = by & 31;
    float* tok = pass ? d_tokc : d_tokx;
    float* cs  = pass ? d_csc  : d_csx;
    const int b = bh >> 3, h = bh & 7;
    const int n0 = blockIdx.x * 1024;
    const int t = threadIdx.x;
    const int w = t >> 5, lane = t & 31;
    const int wg = (w & 1) * 32;
    const int wc = (w >> 1) * 16;
    const int lg = lane >> 3, l8 = lane & 7;

    const int rowA = (lg >> 1) * 8 + l8;
    uint32_t offA[2];
#pragma unroll
    for (int mi = 0; mi < 2; mi++) {
        int goff = wg + mi * 16 + (lg & 1) * 8;
        offA[mi] = rowA * 128 + ((goff * 2) ^ ((rowA & 7) << 4));
    }
    const int rowB = (lg & 1) * 8 + l8;
    const int coff = wc + (lg >> 1) * 8;
    const uint32_t offB = rowB * 128 + ((coff * 2) ^ ((rowB & 7) << 4));

    const bool do_cs = (w < 2);
    float cs0[2] = {0.f, 0.f}, cs1[2] = {0.f, 0.f};

    float c[2][2][4];
#pragma unroll
    for (int mi = 0; mi < 2; mi++)
#pragma unroll
        for (int ni = 0; ni < 2; ni++)
#pragma unroll
            for (int q = 0; q < 4; q++) c[mi][ni][q] = 0.f;

    const size_t swoff = (size_t)pass * PASS_SW;
    const size_t fxoff = (size_t)pass * ROWS_ * 512;

#define TOK_ISSUE(ch, s) \
    { \
        uint32_t so = sb + (uint32_t)(s) * TOK_STAGE; \
        const int nn = n0 + (ch) * 64; \
        _Pragma("unroll") for (int i = 0; i < 2; i++) { \
            int e = i * 256 + t, r = e >> 3, q = e & 7; \
            uint32_t off = SWX(r, q * 16); \
            size_t sidx = swoff + ((size_t)bh * N_ + nn + r) * 64 + q * 8; \
            cpa16(so + off,         &d_sw_h[sidx]); \
            cpa16(so + 8192 + off,  &d_sw_l[sidx]); \
            size_t fidx = fxoff + ((size_t)(b * N_ + nn + r)) * 512 + h * 64 + q * 8; \
            cpa16(so + 16384 + off, &d_fx_h[fidx]); \
            cpa16(so + 24576 + off, &d_fx_l[fidx]); \
        } \
    }

    TOK_ISSUE(0, 0);
    CP_COMMIT();
    TOK_ISSUE(1, 1);
    CP_COMMIT();
    for (int ch = 0; ch < 16; ch++) {
        CP_WAIT1();
        __syncthreads();
        const uint32_t so = (uint32_t)(ch % 3) * TOK_STAGE;
#pragma unroll
        for (int ks = 0; ks < 4; ks++) {
            const uint32_t kso = so + ks * 2048;
            uint32_t ah[2][4], al[2][4], rbh[4], rbl[4];
#pragma unroll
            for (int mi = 0; mi < 2; mi++) {
                ldsm4t(ah[mi], sb + kso + offA[mi]);
                ldsm4t(al[mi], sb + 8192 + kso + offA[mi]);
            }
            if (do_cs) {
#pragma unroll
                for (int mi = 0; mi < 2; mi++) {
                    cs0[mi] += sum2bf(ah[mi][0]) + sum2bf(ah[mi][2])
                             + sum2bf(al[mi][0]) + sum2bf(al[mi][2]);
                    cs1[mi] += sum2bf(ah[mi][1]) + sum2bf(ah[mi][3])
                             + sum2bf(al[mi][1]) + sum2bf(al[mi][3]);
                }
            }
            ldsm4t(rbh, sb + 16384 + kso + offB);
            ldsm4t(rbl, sb + 24576 + kso + offB);
            uint32_t bfh[2][2] = {{rbh[0], rbh[1]}, {rbh[2], rbh[3]}};
            uint32_t bfl[2][2] = {{rbl[0], rbl[1]}, {rbl[2], rbl[3]}};
#pragma unroll
            for (int mi = 0; mi < 2; mi++)
#pragma unroll
                for (int ni = 0; ni < 2; ni++) {
                    mma16816(c[mi][ni], ah[mi], bfh[ni]);
                    mma16816(c[mi][ni], ah[mi], bfl[ni]);
                    mma16816(c[mi][ni], al[mi], bfh[ni]);
                }
        }
        if (ch + 2 < 16) { TOK_ISSUE(ch + 2, (ch + 2) % 3); }
        CP_COMMIT();
    }
#undef TOK_ISSUE
    const int grow = lane >> 2, cpair = (lane & 3) * 2;
#pragma unroll
    for (int mi = 0; mi < 2; mi++) {
        int gg = wg + mi * 16 + grow;
#pragma unroll
        for (int ni = 0; ni < 2; ni++) {
            int col = wc + ni * 8 + cpair;
            atomicAdd(&tok[bh * 4096 + gg * 64 + col],       c[mi][ni][0]);
            atomicAdd(&tok[bh * 4096 + gg * 64 + col + 1],   c[mi][ni][1]);
            atomicAdd(&tok[bh * 4096 + (gg + 8) * 64 + col],     c[mi][ni][2]);
            atomicAdd(&tok[bh * 4096 + (gg + 8) * 64 + col + 1], c[mi][ni][3]);
        }
    }
    if (do_cs) {
#pragma unroll
        for (int mi = 0; mi < 2; mi++) {
            cs0[mi] += __shfl_xor_sync(0xffffffffu, cs0[mi], 1);
            cs0[mi] += __shfl_xor_sync(0xffffffffu, cs0[mi], 2);
            cs1[mi] += __shfl_xor_sync(0xffffffffu, cs1[mi], 1);
            cs1[mi] += __shfl_xor_sync(0xffffffffu, cs1[mi], 2);
            if ((lane & 3) == 0) {
                int gg = wg + mi * 16 + grow;
                atomicAdd(&cs[bh * 64 + gg],     cs0[mi]);
                atomicAdd(&cs[bh * 64 + gg + 8], cs1[mi]);
            }
        }
    }
}

// ================= prep kernels =================
__global__ void presplit2(const float* __restrict__ X0, const float* __restrict__ X1) {
    const int blk = blockIdx.x;
    const float* X = (blk < 32768) ? X0 : X1;
    size_t li = (size_t)(blk & 32767) * 256 + threadIdx.x;
    size_t gi = (size_t)blk * 256 + threadIdx.x;
    float4 v = ((const float4*)X)[li];
    uint2 hh, ll;
    split2(v.x, v.y, hh.x, ll.x);
    split2(v.z, v.w, hh.y, ll.y);
    ((uint2*)d_xs_h)[gi] = hh;
    ((uint2*)d_xs_l)[gi] = ll;
}

// merged weight prep: blocks [0,512) do Wfx split + token-accumulator zeroing,
// blocks [512,1024) do Wls = Wx@Wslice split + bls.
__global__ void prep_weights(const float* __restrict__ Wfx,
                             const float* __restrict__ Wx,
                             const float* __restrict__ Wslice,
                             const float* __restrict__ bx,
                             const float* __restrict__ bslice) {
    extern __shared__ float sm[];
    const int blk = blockIdx.x;
    const int t = threadIdx.x;
    if (blk < 512) {
        int j = blk, cc = t;
        float wv = Wfx[cc * 512 + j];
        __nv_bfloat16 h = __float2bfloat16(wv);
        d_wfx_h[j * 256 + cc] = h;
        d_wfx_l[j * 256 + cc] = __float2bfloat16(wv - __bfloat162float(h));
        int i = j * 256 + cc;
        d_tokx[i] = 0.f; d_tokc[i] = 0.f;
        if (i < BH_ * M_) { d_csx[i] = 0.f; d_csc[i] = 0.f; }
    } else {
        float* ws = sm;
        float* wx = sm + 64;
        int j = blk - 512, h = j >> 6, m = j & 63;
        if (t < 64) ws[t] = Wslice[t * 64 + m];
        for (int i = t; i < 256 * 16; i += 256) {
            int r = i >> 4, q = i & 15;
            *(float4*)&wx[r * 68 + q * 4] = *(const float4*)&Wx[r * 512 + h * 64 + q * 4];
        }
        __syncthreads();
        float acc = 0.f;
#pragma unroll 8
        for (int e = 0; e < 64; e++) acc += wx[t * 68 + e] * ws[e];
        __nv_bfloat16 hh = __float2bfloat16(acc);
        d_wls_h[j * 256 + t] = hh;
        d_wls_l[j * 256 + t] = __float2bfloat16(acc - __bfloat162float(hh));
        if (t == 0) {
            float bb = bslice[m];
            for (int e = 0; e < 64; e++) bb += bx[h * 64 + e] * ws[e];
            d_bls[j] = bb;
        }
    }
}

// ================= tiny attention + fused Wo refactor =================
__global__ void attn_kernel(const float* __restrict__ Wq,
                            const float* __restrict__ Wk,
                            const float* __restrict__ Wv) {
    extern __shared__ float sm[];
    float* A  = sm;
    float* Ks = sm + 64 * 65;
    float* Vs = Ks + 64 * 64;
    const int bh = blockIdx.x;
    const int g = threadIdx.x;

    for (int idx = g; idx < 4096; idx += 64) {
        int r = idx >> 6, cc = idx & 63;
        A[r * 65 + cc] = d_tokc[bh * 4096 + idx] / (d_csc[bh * 64 + r] + 1e-5f);
    }
    __syncthreads();
    {
        float ka[64], va[64];
#pragma unroll
        for (int cc = 0; cc < 64; cc++) { ka[cc] = 0.f; va[cc] = 0.f; }
        for (int e = 0; e < 64; e++) {
            float te = A[g * 65 + e];
#pragma unroll
            for (int cc = 0; cc < 64; cc++) {
                ka[cc] += te * Wk[e * 64 + cc];
                va[cc] += te * Wv[e * 64 + cc];
            }
        }
#pragma unroll
        for (int cc = 0; cc < 64; cc++) { Ks[g * 64 + cc] = ka[cc]; Vs[g * 64 + cc] = va[cc]; }
    }
    __syncthreads();
    for (int idx = g; idx < 4096; idx += 64) {
        int r = idx >> 6, cc = idx & 63;
        A[r * 65 + cc] = d_tokx[bh * 4096 + idx] / (d_csx[bh * 64 + r] + 1e-5f);
    }
    __syncthreads();

    float q[64];
#pragma unroll
    for (int cc = 0; cc < 64; cc++) q[cc] = 0.f;
    for (int e = 0; e < 64; e++) {
        float te = A[g * 65 + e];
#pragma unroll
        for (int cc = 0; cc < 64; cc++) q[cc] += te * Wq[e * 64 + cc];
    }
    __syncthreads();
    float* srow = &A[g * 65];
    float mx = -1e30f;
    for (int m = 0; m < 64; m++) {
        float a2 = 0.f;
#pragma unroll
        for (int cc = 0; cc < 64; cc++) a2 += q[cc] * Ks[m * 64 + cc];
        a2 *= 0.125f;
        srow[m] = a2;
        mx = fmaxf(mx, a2);
    }
    float sum = 0.f;
    for (int m = 0; m < 64; m++) { float e = __expf(srow[m] - mx); srow[m] = e; sum += e; }
    float inv = 1.f / sum;
    float o[64];
#pragma unroll
    for (int cc = 0; cc < 64; cc++) o[cc] = 0.f;
    for (int m = 0; m < 64; m++) {
        float p = srow[m] * inv;
#pragma unroll
        for (int cc = 0; cc < 64; cc++) o[cc] += p * Vs[m * 64 + cc];
    }
    float invx = 1.f / (d_csx[bh * 64 + g] + 1e-5f);
#pragma unroll
    for (int cc = 0; cc < 64; cc++) d_outsc[bh * 4096 + g * 64 + cc] = o[cc] * invx;
}

// wot + split-transpose fused: writes d_wot_h/l[b][cc][hg] directly
__global__ __launch_bounds__(256) void wot_kernel(const float* __restrict__ Wo) {
    const int bhg = blockIdx.x;
    const int b = bhg >> 9;
    const int hg = bhg & 511;
    const int h = hg >> 6;
    __shared__ float orow[64];
    const int t = threadIdx.x;
    if (t < 64) orow[t] = d_outsc[bhg * 64 + t];
    __syncthreads();
    float acc = 0.f;
#pragma unroll 8
    for (int cc = 0; cc < 64; cc++) acc += orow[cc] * Wo[(h * 64 + cc) * 256 + t];
    __nv_bfloat16 hh = __float2bfloat16(acc);
    d_wot_h[((size_t)b * 256 + t) * 512 + hg] = hh;
    d_wot_l[((size_t)b * 256 + t) * 512 + hg] = __float2bfloat16(acc - __bfloat162float(hh));
}

// ================= launcher =================
extern "C" void kernel_launch(void* const* d_in, const int* in_sizes, int n_in,
                              void* d_out, int out_size) {
    const float* x      = (const float*)d_in[0];
    const float* xc     = (const float*)d_in[1];
    const float* Wfx    = (const float*)d_in[2];
    const float* bfx    = (const float*)d_in[3];
    const float* Wx     = (const float*)d_in[4];
    const float* bx     = (const float*)d_in[5];
    const float* Wslice = (const float*)d_in[6];
    const float* bslice = (const float*)d_in[7];
    const float* temp   = (const float*)d_in[8];
    const float* Wq     = (const float*)d_in[9];
    const float* Wk     = (const float*)d_in[10];
    const float* Wv     = (const float*)d_in[11];
    const float* Wo     = (const float*)d_in[12];
    const float* bo     = (const float*)d_in[13];
    float* out = (float*)d_out;

    const int attn_smem = (64 * 65 + 2 * 64 * 64) * (int)sizeof(float);
    const int prep_smem = (64 + 256 * 68) * (int)sizeof(float);
    cudaFuncSetAttribute(attn_kernel,  cudaFuncAttributeMaxDynamicSharedMemorySize, attn_smem);
    cudaFuncSetAttribute(prep_weights, cudaFuncAttributeMaxDynamicSharedMemorySize, prep_smem);
    cudaFuncSetAttribute(proj_mma,     cudaFuncAttributeMaxDynamicSharedMemorySize, GEMM_SMEM);
    cudaFuncSetAttribute(final_mma,    cudaFuncAttributeMaxDynamicSharedMemorySize, GEMM_SMEM);
    cudaFuncSetAttribute(token_mma,    cudaFuncAttributeMaxDynamicSharedMemorySize, TOK_SMEM);

    prep_weights<<<1024, 256, prep_smem>>>(Wfx, Wx, Wslice, bx, bslice);
    presplit2<<<65536, 256>>>(x, xc);
    proj_mma<<<dim3(8, 2 * ROWS_ / 128), 256, GEMM_SMEM>>>(bfx, temp);
    token_mma<<<dim3(32, 64), 256, TOK_SMEM>>>();
    attn_kernel<<<BH_, 64, attn_smem>>>(Wq, Wk, Wv);
    wot_kernel<<<B_ * INNER_, 256>>>(Wo);
    final_mma<<<dim3(2, ROWS_ / 128), 256, GEMM_SMEM>>>(bo, out);
}